// round 4
// baseline (speedup 1.0000x reference)
#include <cuda_runtime.h>
#include <cuda_bf16.h>
#include <cstdint>

#define D 128
#define OUTD 128
#define MAXN 100000
#define EPS 0.1f

// Scratch (allocation-free rule: __device__ globals)
__device__ float g_agg[(size_t)MAXN * D];
__device__ float g_alpha_l[MAXN];
__device__ float g_alpha_r[MAXN];
__device__ int   g_is64;
__device__ uint32_t g_W_hi[D * OUTD];
__device__ uint32_t g_W_lo[D * OUTD];

// ---------------------------------------------------------------------------
// Kernel 0: detect int64 vs int32 edge_index (parallel, one wave of loads).
// int64 values < 2^31 store as [low32, 0] pairs -> all odd words zero.
// ---------------------------------------------------------------------------
__global__ void detect_kernel(const unsigned int* __restrict__ ei_words, int E) {
    __shared__ int bad;
    if (threadIdx.x == 0) bad = 0;
    __syncthreads();
    int nchk = E < 1024 ? E : 1024;
    for (int k = threadIdx.x; k < nchk; k += blockDim.x)
        if (ei_words[2 * k + 1] != 0u) bad = 1;
    __syncthreads();
    if (threadIdx.x == 0) g_is64 = bad ? 0 : 1;
}

// ---------------------------------------------------------------------------
// Kernel 0b: precompute W in tf32 hi/lo (done once; reused by all GEMM CTAs)
// ---------------------------------------------------------------------------
__device__ __forceinline__ uint32_t f2tf32(float f) {
    uint32_t r;
    asm("cvt.rna.tf32.f32 %0, %1;" : "=r"(r) : "f"(f));
    return r;
}

__global__ void wprep_kernel(const float* __restrict__ W) {
    int idx = blockIdx.x * blockDim.x + threadIdx.x;
    if (idx < D * OUTD) {
        float w = W[idx];
        uint32_t hi = f2tf32(w);
        g_W_hi[idx] = hi;
        g_W_lo[idx] = f2tf32(w - __uint_as_float(hi));
    }
}

// ---------------------------------------------------------------------------
// Kernel 1: per-node attention logits + agg = EPS * x_0
// ---------------------------------------------------------------------------
__global__ void alpha_init_kernel(const float* __restrict__ x,
                                  const float* __restrict__ x0,
                                  const float* __restrict__ att_l,
                                  const float* __restrict__ att_r,
                                  int N) {
    int warp = (blockIdx.x * blockDim.x + threadIdx.x) >> 5;
    int lane = threadIdx.x & 31;
    if (warp >= N) return;

    float4 xv = reinterpret_cast<const float4*>(x + (size_t)warp * D)[lane];
    float4 al = reinterpret_cast<const float4*>(att_l)[lane];
    float4 ar = reinterpret_cast<const float4*>(att_r)[lane];

    float sl = xv.x * al.x + xv.y * al.y + xv.z * al.z + xv.w * al.w;
    float sr = xv.x * ar.x + xv.y * ar.y + xv.z * ar.z + xv.w * ar.w;
#pragma unroll
    for (int o = 16; o > 0; o >>= 1) {
        sl += __shfl_xor_sync(0xffffffffu, sl, o);
        sr += __shfl_xor_sync(0xffffffffu, sr, o);
    }
    if (lane == 0) {
        g_alpha_l[warp] = sl;
        g_alpha_r[warp] = sr;
    }

    float4 x0v = reinterpret_cast<const float4*>(x0 + (size_t)warp * D)[lane];
    float4 outv = make_float4(EPS * x0v.x, EPS * x0v.y, EPS * x0v.z, EPS * x0v.w);
    reinterpret_cast<float4*>(g_agg + (size_t)warp * D)[lane] = outv;
}

// ---------------------------------------------------------------------------
// Kernel 2: per-edge gather + scatter-add (coalesced metadata, shfl broadcast)
// ---------------------------------------------------------------------------
__global__ void scatter_kernel(const float* __restrict__ x,
                               const void* __restrict__ ei_raw,
                               const float* __restrict__ ew,
                               int E) {
    int warp = (blockIdx.x * blockDim.x + threadIdx.x) >> 5;
    int lane = threadIdx.x & 31;
    int base = warp * 32;
    if (base >= E) return;

    int e = base + lane;
    int src = 0, dst = 0;
    float c = 0.f;
    if (e < E) {
        if (g_is64) {
            const long long* ei = (const long long*)ei_raw;
            src = (int)ei[e];
            dst = (int)ei[(size_t)E + e];
        } else {
            const int* ei = (const int*)ei_raw;
            src = ei[e];
            dst = ei[(size_t)E + e];
        }
        c = tanhf(g_alpha_l[src] + g_alpha_r[dst]) * ew[e];
    }

    int nvalid = E - base;
    if (nvalid > 32) nvalid = 32;
    for (int j = 0; j < nvalid; j++) {
        int s    = __shfl_sync(0xffffffffu, src, j);
        int d    = __shfl_sync(0xffffffffu, dst, j);
        float cc = __shfl_sync(0xffffffffu, c, j);
        float4 xv = reinterpret_cast<const float4*>(x + (size_t)s * D)[lane];
        float* p = g_agg + (size_t)d * D + lane * 4;
        asm volatile("red.global.add.v4.f32 [%0], {%1, %2, %3, %4};"
                     :: "l"(p), "f"(xv.x * cc), "f"(xv.y * cc),
                        "f"(xv.z * cc), "f"(xv.w * cc)
                     : "memory");
    }
}

// ---------------------------------------------------------------------------
// Kernel 3: out = relu(agg) @ W^T + b via 3xTF32 mma.sync, persistent blocks.
// grid=148, 256 threads. W hi/lo loaded to smem ONCE per block (no convert).
// Loop over 64-row A tiles; full K=128 per tile; warp grid 2(M) x 4(N).
// ---------------------------------------------------------------------------
#define WPAD 132   // 128 + 4 pad -> conflict-free fragment loads

// smem words: W hi/lo: 128*132 each; A hi/lo: 64*132 each
#define SM_WHI 0
#define SM_WLO (128 * WPAD)
#define SM_AHI (2 * 128 * WPAD)
#define SM_ALO (2 * 128 * WPAD + 64 * WPAD)
#define SM_WORDS (2 * 128 * WPAD + 2 * 64 * WPAD)

__device__ __forceinline__ void mma_tf32(float* d, const uint32_t* a, const uint32_t* b) {
    asm volatile(
        "mma.sync.aligned.m16n8k8.row.col.f32.tf32.tf32.f32 "
        "{%0,%1,%2,%3}, {%4,%5,%6,%7}, {%8,%9}, {%0,%1,%2,%3};"
        : "+f"(d[0]), "+f"(d[1]), "+f"(d[2]), "+f"(d[3])
        : "r"(a[0]), "r"(a[1]), "r"(a[2]), "r"(a[3]), "r"(b[0]), "r"(b[1]));
}

__global__ __launch_bounds__(256, 1)
void gemm_kernel(const float* __restrict__ bias,
                 float* __restrict__ out,
                 int N) {
    extern __shared__ uint32_t sm[];
    int tid = threadIdx.x;
    int lane = tid & 31;
    int wid = tid >> 5;
    int warpM = wid >> 2;   // 0..1 (32 rows each)
    int warpN = wid & 3;    // 0..3 (32 cols each)

    // ---- load W hi/lo into smem once (vectorized, padded rows) ----
    for (int i = tid; i < 128 * 32; i += 256) {
        int r = i >> 5;
        int c4 = i & 31;
        float4 h = reinterpret_cast<const float4*>(g_W_hi)[(size_t)r * 32 + c4];
        float4 l = reinterpret_cast<const float4*>(g_W_lo)[(size_t)r * 32 + c4];
        *reinterpret_cast<float4*>(&sm[SM_WHI + r * WPAD + c4 * 4]) = h;
        *reinterpret_cast<float4*>(&sm[SM_WLO + r * WPAD + c4 * 4]) = l;
    }

    // bias for this warp's columns (cols fixed across tiles)
    float bv[4][2];
#pragma unroll
    for (int nt = 0; nt < 4; nt++) {
        int col = warpN * 32 + nt * 8 + (lane & 3) * 2;
        bv[nt][0] = bias[col];
        bv[nt][1] = bias[col + 1];
    }
    __syncthreads();

    int ntiles = (N + 63) >> 6;
    for (int t = blockIdx.x; t < ntiles; t += gridDim.x) {
        int m0 = t << 6;

        // ---- fill A tile: relu + tf32 hi/lo split ----
        for (int i = tid; i < 64 * 32; i += 256) {
            int r = i >> 5;
            int c4 = i & 31;
            int row = m0 + r;
            float4 v;
            if (row < N)
                v = *reinterpret_cast<const float4*>(g_agg + (size_t)row * D + c4 * 4);
            else
                v = make_float4(0.f, 0.f, 0.f, 0.f);
            float a0 = fmaxf(v.x, 0.f), a1 = fmaxf(v.y, 0.f);
            float a2 = fmaxf(v.z, 0.f), a3 = fmaxf(v.w, 0.f);
            uint32_t h0 = f2tf32(a0), h1 = f2tf32(a1), h2 = f2tf32(a2), h3 = f2tf32(a3);
            uint4 hv = make_uint4(h0, h1, h2, h3);
            uint4 lv = make_uint4(f2tf32(a0 - __uint_as_float(h0)),
                                  f2tf32(a1 - __uint_as_float(h1)),
                                  f2tf32(a2 - __uint_as_float(h2)),
                                  f2tf32(a3 - __uint_as_float(h3)));
            *reinterpret_cast<uint4*>(&sm[SM_AHI + r * WPAD + c4 * 4]) = hv;
            *reinterpret_cast<uint4*>(&sm[SM_ALO + r * WPAD + c4 * 4]) = lv;
        }
        __syncthreads();

        // ---- compute: 16 k-steps over full K=128 ----
        float acc[2][4][4];
#pragma unroll
        for (int mt = 0; mt < 2; mt++)
#pragma unroll
            for (int nt = 0; nt < 4; nt++)
#pragma unroll
                for (int i = 0; i < 4; i++) acc[mt][nt][i] = 0.f;

#pragma unroll
        for (int ks = 0; ks < 16; ks++) {
            int c = ks * 8 + (lane & 3);
            uint32_t ahi[2][4], alo[2][4];
#pragma unroll
            for (int mt = 0; mt < 2; mt++) {
                int r = warpM * 32 + mt * 16 + (lane >> 2);
                ahi[mt][0] = sm[SM_AHI + r * WPAD + c];
                ahi[mt][1] = sm[SM_AHI + (r + 8) * WPAD + c];
                ahi[mt][2] = sm[SM_AHI + r * WPAD + c + 4];
                ahi[mt][3] = sm[SM_AHI + (r + 8) * WPAD + c + 4];
                alo[mt][0] = sm[SM_ALO + r * WPAD + c];
                alo[mt][1] = sm[SM_ALO + (r + 8) * WPAD + c];
                alo[mt][2] = sm[SM_ALO + r * WPAD + c + 4];
                alo[mt][3] = sm[SM_ALO + (r + 8) * WPAD + c + 4];
            }
            uint32_t bhi[4][2], blo[4][2];
#pragma unroll
            for (int nt = 0; nt < 4; nt++) {
                int n = warpN * 32 + nt * 8 + (lane >> 2);
                bhi[nt][0] = sm[SM_WHI + n * WPAD + c];
                bhi[nt][1] = sm[SM_WHI + n * WPAD + c + 4];
                blo[nt][0] = sm[SM_WLO + n * WPAD + c];
                blo[nt][1] = sm[SM_WLO + n * WPAD + c + 4];
            }
#pragma unroll
            for (int mt = 0; mt < 2; mt++)
#pragma unroll
                for (int nt = 0; nt < 4; nt++) {
                    mma_tf32(acc[mt][nt], ahi[mt], blo[nt]);
                    mma_tf32(acc[mt][nt], alo[mt], bhi[nt]);
                    mma_tf32(acc[mt][nt], ahi[mt], bhi[nt]);
                }
        }

        // ---- epilogue ----
#pragma unroll
        for (int mt = 0; mt < 2; mt++) {
            int r0 = m0 + warpM * 32 + mt * 16 + (lane >> 2);
#pragma unroll
            for (int nt = 0; nt < 4; nt++) {
                int col = warpN * 32 + nt * 8 + (lane & 3) * 2;
                if (r0 < N) {
                    float2 v = make_float2(acc[mt][nt][0] + bv[nt][0],
                                           acc[mt][nt][1] + bv[nt][1]);
                    *reinterpret_cast<float2*>(out + (size_t)r0 * OUTD + col) = v;
                }
                if (r0 + 8 < N) {
                    float2 v = make_float2(acc[mt][nt][2] + bv[nt][0],
                                           acc[mt][nt][3] + bv[nt][1]);
                    *reinterpret_cast<float2*>(out + (size_t)(r0 + 8) * OUTD + col) = v;
                }
            }
        }
        __syncthreads();  // protect smem A before next fill
    }
}

// ---------------------------------------------------------------------------
// Launch
// inputs: 0 x [N,128], 1 x_0 [N,128], 2 edge_weight [E], 3 att_l [128],
//         4 att_r [128], 5 W [128,128], 6 b [128], 7 edge_index [2,E]
// ---------------------------------------------------------------------------
extern "C" void kernel_launch(void* const* d_in, const int* in_sizes, int n_in,
                              void* d_out, int out_size) {
    const float* x      = (const float*)d_in[0];
    const float* x0     = (const float*)d_in[1];
    const float* ew     = (const float*)d_in[2];
    const float* att_l  = (const float*)d_in[3];
    const float* att_r  = (const float*)d_in[4];
    const float* W      = (const float*)d_in[5];
    const float* bias   = (const float*)d_in[6];
    const void*  ei     = (const void*)d_in[7];
    float* out = (float*)d_out;

    int N = in_sizes[1] / D;
    int E = in_sizes[2];

    static bool attr_set = false;
    if (!attr_set) {
        cudaFuncSetAttribute(gemm_kernel,
                             cudaFuncAttributeMaxDynamicSharedMemorySize,
                             SM_WORDS * 4);
        attr_set = true;
    }

    detect_kernel<<<1, 256>>>((const unsigned int*)ei, E);
    wprep_kernel<<<64, 256>>>(W);
    {
        int blocks = (N + 7) / 8;
        alpha_init_kernel<<<blocks, 256>>>(x, x0, att_l, att_r, N);
    }
    {
        int warps = (E + 31) / 32;
        int blocks = (warps + 7) / 8;
        scatter_kernel<<<blocks, 256>>>(x, ei, ew, E);
    }
    gemm_kernel<<<148, 256, SM_WORDS * 4>>>(bias, out, N);
}

// round 5
// speedup vs baseline: 1.0040x; 1.0040x over previous
#include <cuda_runtime.h>
#include <cuda_bf16.h>
#include <cstdint>

#define D 128
#define OUTD 128
#define MAXN 100000
#define EPS 0.1f
#define CAP 48   // per-dst bucket capacity (avg in-degree 6.4; overflow ~impossible)

// Scratch (allocation-free rule: __device__ globals)
__device__ float g_agg[(size_t)MAXN * D];
__device__ float g_alpha_l[MAXN];
__device__ float g_alpha_r[MAXN];
__device__ int   g_is64;
__device__ uint32_t g_W_hi[D * OUTD];
__device__ uint32_t g_W_lo[D * OUTD];
__device__ int   g_cnt[MAXN];
__device__ uint2 g_bucket[(size_t)MAXN * CAP];  // (src, coeff bits)

// ---------------------------------------------------------------------------
// Kernel 0: detect int64 vs int32 edge_index (parallel).
// ---------------------------------------------------------------------------
__global__ void detect_kernel(const unsigned int* __restrict__ ei_words, int E) {
    __shared__ int bad;
    if (threadIdx.x == 0) bad = 0;
    __syncthreads();
    int nchk = E < 1024 ? E : 1024;
    for (int k = threadIdx.x; k < nchk; k += blockDim.x)
        if (ei_words[2 * k + 1] != 0u) bad = 1;
    __syncthreads();
    if (threadIdx.x == 0) g_is64 = bad ? 0 : 1;
}

// ---------------------------------------------------------------------------
// Kernel 0b: precompute W in tf32 hi/lo
// ---------------------------------------------------------------------------
__device__ __forceinline__ uint32_t f2tf32(float f) {
    uint32_t r;
    asm("cvt.rna.tf32.f32 %0, %1;" : "=r"(r) : "f"(f));
    return r;
}

__global__ void wprep_kernel(const float* __restrict__ W) {
    int idx = blockIdx.x * blockDim.x + threadIdx.x;
    if (idx < D * OUTD) {
        float w = W[idx];
        uint32_t hi = f2tf32(w);
        g_W_hi[idx] = hi;
        g_W_lo[idx] = f2tf32(w - __uint_as_float(hi));
    }
}

// ---------------------------------------------------------------------------
// Kernel 0c: zero per-node counters
// ---------------------------------------------------------------------------
__global__ void zero_kernel(int N) {
    int i = blockIdx.x * blockDim.x + threadIdx.x;
    if (i < N) g_cnt[i] = 0;
}

// ---------------------------------------------------------------------------
// Kernel 1: per-node attention logits + agg = EPS * x_0
// ---------------------------------------------------------------------------
__global__ void alpha_init_kernel(const float* __restrict__ x,
                                  const float* __restrict__ x0,
                                  const float* __restrict__ att_l,
                                  const float* __restrict__ att_r,
                                  int N) {
    int warp = (blockIdx.x * blockDim.x + threadIdx.x) >> 5;
    int lane = threadIdx.x & 31;
    if (warp >= N) return;

    float4 xv = reinterpret_cast<const float4*>(x + (size_t)warp * D)[lane];
    float4 al = reinterpret_cast<const float4*>(att_l)[lane];
    float4 ar = reinterpret_cast<const float4*>(att_r)[lane];

    float sl = xv.x * al.x + xv.y * al.y + xv.z * al.z + xv.w * al.w;
    float sr = xv.x * ar.x + xv.y * ar.y + xv.z * ar.z + xv.w * ar.w;
#pragma unroll
    for (int o = 16; o > 0; o >>= 1) {
        sl += __shfl_xor_sync(0xffffffffu, sl, o);
        sr += __shfl_xor_sync(0xffffffffu, sr, o);
    }
    if (lane == 0) {
        g_alpha_l[warp] = sl;
        g_alpha_r[warp] = sr;
    }

    float4 x0v = reinterpret_cast<const float4*>(x0 + (size_t)warp * D)[lane];
    float4 outv = make_float4(EPS * x0v.x, EPS * x0v.y, EPS * x0v.z, EPS * x0v.w);
    reinterpret_cast<float4*>(g_agg + (size_t)warp * D)[lane] = outv;
}

// ---------------------------------------------------------------------------
// Kernel 2a: fill per-dst buckets with (src, coeff). Thread per edge.
// Overflow (slot >= CAP) falls back to direct atomic adds into agg.
// ---------------------------------------------------------------------------
__global__ void fill_kernel(const float* __restrict__ x,
                            const void* __restrict__ ei_raw,
                            const float* __restrict__ ew,
                            int E) {
    int e = blockIdx.x * blockDim.x + threadIdx.x;
    if (e >= E) return;

    int src, dst;
    if (g_is64) {
        const long long* ei = (const long long*)ei_raw;
        src = (int)ei[e];
        dst = (int)ei[(size_t)E + e];
    } else {
        const int* ei = (const int*)ei_raw;
        src = ei[e];
        dst = ei[(size_t)E + e];
    }
    float c = tanhf(g_alpha_l[src] + g_alpha_r[dst]) * ew[e];

    int slot = atomicAdd(&g_cnt[dst], 1);
    if (slot < CAP) {
        g_bucket[(size_t)dst * CAP + slot] = make_uint2((unsigned)src, __float_as_uint(c));
    } else {
        // essentially-never fallback: direct atomic add of c * x[src]
        const float4* xr = reinterpret_cast<const float4*>(x + (size_t)src * D);
        float* p = g_agg + (size_t)dst * D;
        for (int i = 0; i < 32; i++) {
            float4 v = xr[i];
            asm volatile("red.global.add.v4.f32 [%0], {%1, %2, %3, %4};"
                         :: "l"(p + i * 4), "f"(v.x * c), "f"(v.y * c),
                            "f"(v.z * c), "f"(v.w * c)
                         : "memory");
        }
    }
}

// ---------------------------------------------------------------------------
// Kernel 2b: pull. One warp per dst node: accumulate in registers, single
// red.global.add.v4 per lane into agg (composes with overflow fallback).
// ---------------------------------------------------------------------------
__global__ void pull_kernel(const float* __restrict__ x, int N) {
    int node = (blockIdx.x * blockDim.x + threadIdx.x) >> 5;
    int lane = threadIdx.x & 31;
    if (node >= N) return;

    int cnt = g_cnt[node];
    if (cnt > CAP) cnt = CAP;
    if (cnt == 0) return;

    const uint2* b = g_bucket + (size_t)node * CAP;
    float ax = 0.f, ay = 0.f, az = 0.f, aw = 0.f;
    for (int j = 0; j < cnt; j++) {
        uint2 p = b[j];  // lane-uniform -> broadcast
        float c = __uint_as_float(p.y);
        float4 xv = reinterpret_cast<const float4*>(x + (size_t)p.x * D)[lane];
        ax += c * xv.x;
        ay += c * xv.y;
        az += c * xv.z;
        aw += c * xv.w;
    }
    float* p = g_agg + (size_t)node * D + lane * 4;
    asm volatile("red.global.add.v4.f32 [%0], {%1, %2, %3, %4};"
                 :: "l"(p), "f"(ax), "f"(ay), "f"(az), "f"(aw)
                 : "memory");
}

// ---------------------------------------------------------------------------
// Kernel 3: out = relu(agg) @ W^T + b via 3xTF32 mma.sync, persistent blocks.
// ---------------------------------------------------------------------------
#define WPAD 132

#define SM_WHI 0
#define SM_WLO (128 * WPAD)
#define SM_AHI (2 * 128 * WPAD)
#define SM_ALO (2 * 128 * WPAD + 64 * WPAD)
#define SM_WORDS (2 * 128 * WPAD + 2 * 64 * WPAD)

__device__ __forceinline__ void mma_tf32(float* d, const uint32_t* a, const uint32_t* b) {
    asm volatile(
        "mma.sync.aligned.m16n8k8.row.col.f32.tf32.tf32.f32 "
        "{%0,%1,%2,%3}, {%4,%5,%6,%7}, {%8,%9}, {%0,%1,%2,%3};"
        : "+f"(d[0]), "+f"(d[1]), "+f"(d[2]), "+f"(d[3])
        : "r"(a[0]), "r"(a[1]), "r"(a[2]), "r"(a[3]), "r"(b[0]), "r"(b[1]));
}

__global__ __launch_bounds__(256, 1)
void gemm_kernel(const float* __restrict__ bias,
                 float* __restrict__ out,
                 int N) {
    extern __shared__ uint32_t sm[];
    int tid = threadIdx.x;
    int lane = tid & 31;
    int wid = tid >> 5;
    int warpM = wid >> 2;   // 0..1
    int warpN = wid & 3;    // 0..3

    for (int i = tid; i < 128 * 32; i += 256) {
        int r = i >> 5;
        int c4 = i & 31;
        float4 h = reinterpret_cast<const float4*>(g_W_hi)[(size_t)r * 32 + c4];
        float4 l = reinterpret_cast<const float4*>(g_W_lo)[(size_t)r * 32 + c4];
        *reinterpret_cast<float4*>(&sm[SM_WHI + r * WPAD + c4 * 4]) = h;
        *reinterpret_cast<float4*>(&sm[SM_WLO + r * WPAD + c4 * 4]) = l;
    }

    float bv[4][2];
#pragma unroll
    for (int nt = 0; nt < 4; nt++) {
        int col = warpN * 32 + nt * 8 + (lane & 3) * 2;
        bv[nt][0] = bias[col];
        bv[nt][1] = bias[col + 1];
    }
    __syncthreads();

    int ntiles = (N + 63) >> 6;
    for (int t = blockIdx.x; t < ntiles; t += gridDim.x) {
        int m0 = t << 6;

        for (int i = tid; i < 64 * 32; i += 256) {
            int r = i >> 5;
            int c4 = i & 31;
            int row = m0 + r;
            float4 v;
            if (row < N)
                v = *reinterpret_cast<const float4*>(g_agg + (size_t)row * D + c4 * 4);
            else
                v = make_float4(0.f, 0.f, 0.f, 0.f);
            float a0 = fmaxf(v.x, 0.f), a1 = fmaxf(v.y, 0.f);
            float a2 = fmaxf(v.z, 0.f), a3 = fmaxf(v.w, 0.f);
            uint32_t h0 = f2tf32(a0), h1 = f2tf32(a1), h2 = f2tf32(a2), h3 = f2tf32(a3);
            uint4 hv = make_uint4(h0, h1, h2, h3);
            uint4 lv = make_uint4(f2tf32(a0 - __uint_as_float(h0)),
                                  f2tf32(a1 - __uint_as_float(h1)),
                                  f2tf32(a2 - __uint_as_float(h2)),
                                  f2tf32(a3 - __uint_as_float(h3)));
            *reinterpret_cast<uint4*>(&sm[SM_AHI + r * WPAD + c4 * 4]) = hv;
            *reinterpret_cast<uint4*>(&sm[SM_ALO + r * WPAD + c4 * 4]) = lv;
        }
        __syncthreads();

        float acc[2][4][4];
#pragma unroll
        for (int mt = 0; mt < 2; mt++)
#pragma unroll
            for (int nt = 0; nt < 4; nt++)
#pragma unroll
                for (int i = 0; i < 4; i++) acc[mt][nt][i] = 0.f;

#pragma unroll
        for (int ks = 0; ks < 16; ks++) {
            int c = ks * 8 + (lane & 3);
            uint32_t ahi[2][4], alo[2][4];
#pragma unroll
            for (int mt = 0; mt < 2; mt++) {
                int r = warpM * 32 + mt * 16 + (lane >> 2);
                ahi[mt][0] = sm[SM_AHI + r * WPAD + c];
                ahi[mt][1] = sm[SM_AHI + (r + 8) * WPAD + c];
                ahi[mt][2] = sm[SM_AHI + r * WPAD + c + 4];
                ahi[mt][3] = sm[SM_AHI + (r + 8) * WPAD + c + 4];
                alo[mt][0] = sm[SM_ALO + r * WPAD + c];
                alo[mt][1] = sm[SM_ALO + (r + 8) * WPAD + c];
                alo[mt][2] = sm[SM_ALO + r * WPAD + c + 4];
                alo[mt][3] = sm[SM_ALO + (r + 8) * WPAD + c + 4];
            }
            uint32_t bhi[4][2], blo[4][2];
#pragma unroll
            for (int nt = 0; nt < 4; nt++) {
                int n = warpN * 32 + nt * 8 + (lane >> 2);
                bhi[nt][0] = sm[SM_WHI + n * WPAD + c];
                bhi[nt][1] = sm[SM_WHI + n * WPAD + c + 4];
                blo[nt][0] = sm[SM_WLO + n * WPAD + c];
                blo[nt][1] = sm[SM_WLO + n * WPAD + c + 4];
            }
#pragma unroll
            for (int mt = 0; mt < 2; mt++)
#pragma unroll
                for (int nt = 0; nt < 4; nt++) {
                    mma_tf32(acc[mt][nt], ahi[mt], blo[nt]);
                    mma_tf32(acc[mt][nt], alo[mt], bhi[nt]);
                    mma_tf32(acc[mt][nt], ahi[mt], bhi[nt]);
                }
        }

#pragma unroll
        for (int mt = 0; mt < 2; mt++) {
            int r0 = m0 + warpM * 32 + mt * 16 + (lane >> 2);
#pragma unroll
            for (int nt = 0; nt < 4; nt++) {
                int col = warpN * 32 + nt * 8 + (lane & 3) * 2;
                if (r0 < N) {
                    float2 v = make_float2(acc[mt][nt][0] + bv[nt][0],
                                           acc[mt][nt][1] + bv[nt][1]);
                    *reinterpret_cast<float2*>(out + (size_t)r0 * OUTD + col) = v;
                }
                if (r0 + 8 < N) {
                    float2 v = make_float2(acc[mt][nt][2] + bv[nt][0],
                                           acc[mt][nt][3] + bv[nt][1]);
                    *reinterpret_cast<float2*>(out + (size_t)(r0 + 8) * OUTD + col) = v;
                }
            }
        }
        __syncthreads();
    }
}

// ---------------------------------------------------------------------------
// Launch
// ---------------------------------------------------------------------------
extern "C" void kernel_launch(void* const* d_in, const int* in_sizes, int n_in,
                              void* d_out, int out_size) {
    const float* x      = (const float*)d_in[0];
    const float* x0     = (const float*)d_in[1];
    const float* ew     = (const float*)d_in[2];
    const float* att_l  = (const float*)d_in[3];
    const float* att_r  = (const float*)d_in[4];
    const float* W      = (const float*)d_in[5];
    const float* bias   = (const float*)d_in[6];
    const void*  ei     = (const void*)d_in[7];
    float* out = (float*)d_out;

    int N = in_sizes[1] / D;
    int E = in_sizes[2];

    static bool attr_set = false;
    if (!attr_set) {
        cudaFuncSetAttribute(gemm_kernel,
                             cudaFuncAttributeMaxDynamicSharedMemorySize,
                             SM_WORDS * 4);
        attr_set = true;
    }

    detect_kernel<<<1, 256>>>((const unsigned int*)ei, E);
    wprep_kernel<<<64, 256>>>(W);
    zero_kernel<<<(N + 255) / 256, 256>>>(N);
    {
        int blocks = (N + 7) / 8;
        alpha_init_kernel<<<blocks, 256>>>(x, x0, att_l, att_r, N);
    }
    fill_kernel<<<(E + 255) / 256, 256>>>(x, ei, ew, E);
    {
        int blocks = (N + 7) / 8;  // warp per node
        pull_kernel<<<blocks, 256>>>(x, N);
    }
    gemm_kernel<<<148, 256, SM_WORDS * 4>>>(bias, out, N);
}

// round 6
// speedup vs baseline: 1.3470x; 1.3417x over previous
#include <cuda_runtime.h>
#include <cuda_bf16.h>
#include <cuda_fp16.h>
#include <cstdint>

#define D 128
#define OUTD 128
#define MAXN 100000
#define EPS 0.1f
#define CAP 48   // per-dst bucket capacity (avg in-degree 6.4)

// Scratch (allocation-free rule: __device__ globals)
__device__ float   g_agg[(size_t)MAXN * D];
__device__ __half  g_x_h[(size_t)MAXN * D];
__device__ float   g_alpha_l[MAXN];
__device__ float   g_alpha_r[MAXN];
__device__ int     g_is64;
__device__ uint32_t g_W_hi[128 * 64];   // bf16x2 packed, [n][k/2]
__device__ uint32_t g_W_lo[128 * 64];
__device__ int     g_cnt[MAXN];
__device__ uint2   g_bucket[(size_t)MAXN * CAP];  // (src, coeff bits)

// ---------------------------------------------------------------------------
// Kernel P: fused prep. blocks [0,32): W -> bf16 hi/lo; [32, 32+NZ): zero cnt;
// last block: int64/int32 detect.
// ---------------------------------------------------------------------------
__global__ void prep_kernel(const float* __restrict__ W,
                            const unsigned int* __restrict__ ei_words,
                            int N, int E, int nzero) {
    int b = blockIdx.x;
    if (b < 32) {
        // W prep: 128*64 packed words
        int idx = b * 256 + threadIdx.x;  // < 8192
        int n = idx >> 6, k2 = idx & 63;
        float w0 = W[n * D + 2 * k2];
        float w1 = W[n * D + 2 * k2 + 1];
        __nv_bfloat16 h0 = __float2bfloat16_rn(w0);
        __nv_bfloat16 h1 = __float2bfloat16_rn(w1);
        float l0 = w0 - __bfloat162float(h0);
        float l1 = w1 - __bfloat162float(h1);
        __nv_bfloat162 hp = __halves2bfloat162(h0, h1);
        __nv_bfloat162 lp = __halves2bfloat162(__float2bfloat16_rn(l0),
                                               __float2bfloat16_rn(l1));
        g_W_hi[idx] = *reinterpret_cast<uint32_t*>(&hp);
        g_W_lo[idx] = *reinterpret_cast<uint32_t*>(&lp);
    } else if (b < 32 + nzero) {
        int i = (b - 32) * 256 + threadIdx.x;
        if (i < N) g_cnt[i] = 0;
    } else {
        __shared__ int bad;
        if (threadIdx.x == 0) bad = 0;
        __syncthreads();
        int nchk = E < 1024 ? E : 1024;
        for (int k = threadIdx.x; k < nchk; k += blockDim.x)
            if (ei_words[2 * k + 1] != 0u) bad = 1;
        __syncthreads();
        if (threadIdx.x == 0) g_is64 = bad ? 0 : 1;
    }
}

// ---------------------------------------------------------------------------
// Kernel 1: alpha logits + agg = EPS*x_0 + write fp16 copy of x
// ---------------------------------------------------------------------------
__global__ void alpha_init_kernel(const float* __restrict__ x,
                                  const float* __restrict__ x0,
                                  const float* __restrict__ att_l,
                                  const float* __restrict__ att_r,
                                  int N) {
    int warp = (blockIdx.x * blockDim.x + threadIdx.x) >> 5;
    int lane = threadIdx.x & 31;
    if (warp >= N) return;

    float4 xv = reinterpret_cast<const float4*>(x + (size_t)warp * D)[lane];
    float4 al = reinterpret_cast<const float4*>(att_l)[lane];
    float4 ar = reinterpret_cast<const float4*>(att_r)[lane];

    float sl = xv.x * al.x + xv.y * al.y + xv.z * al.z + xv.w * al.w;
    float sr = xv.x * ar.x + xv.y * ar.y + xv.z * ar.z + xv.w * ar.w;
#pragma unroll
    for (int o = 16; o > 0; o >>= 1) {
        sl += __shfl_xor_sync(0xffffffffu, sl, o);
        sr += __shfl_xor_sync(0xffffffffu, sr, o);
    }
    if (lane == 0) {
        g_alpha_l[warp] = sl;
        g_alpha_r[warp] = sr;
    }

    // fp16 copy of x for the pull gather
    __half2 h01 = __floats2half2_rn(xv.x, xv.y);
    __half2 h23 = __floats2half2_rn(xv.z, xv.w);
    uint2 hw = make_uint2(*reinterpret_cast<uint32_t*>(&h01),
                          *reinterpret_cast<uint32_t*>(&h23));
    reinterpret_cast<uint2*>(g_x_h + (size_t)warp * D)[lane] = hw;

    float4 x0v = reinterpret_cast<const float4*>(x0 + (size_t)warp * D)[lane];
    float4 outv = make_float4(EPS * x0v.x, EPS * x0v.y, EPS * x0v.z, EPS * x0v.w);
    reinterpret_cast<float4*>(g_agg + (size_t)warp * D)[lane] = outv;
}

// ---------------------------------------------------------------------------
// Kernel 2a: fill per-dst buckets with (src, coeff). Thread per edge.
// ---------------------------------------------------------------------------
__global__ void fill_kernel(const float* __restrict__ x,
                            const void* __restrict__ ei_raw,
                            const float* __restrict__ ew,
                            int E) {
    int e = blockIdx.x * blockDim.x + threadIdx.x;
    if (e >= E) return;

    int src, dst;
    if (g_is64) {
        const long long* ei = (const long long*)ei_raw;
        src = (int)ei[e];
        dst = (int)ei[(size_t)E + e];
    } else {
        const int* ei = (const int*)ei_raw;
        src = ei[e];
        dst = ei[(size_t)E + e];
    }
    float c = tanhf(g_alpha_l[src] + g_alpha_r[dst]) * ew[e];

    int slot = atomicAdd(&g_cnt[dst], 1);
    if (slot < CAP) {
        g_bucket[(size_t)dst * CAP + slot] = make_uint2((unsigned)src, __float_as_uint(c));
    } else {
        // essentially-never fallback: direct fp32 atomic add of c * x[src]
        const float4* xr = reinterpret_cast<const float4*>(x + (size_t)src * D);
        float* p = g_agg + (size_t)dst * D;
        for (int i = 0; i < 32; i++) {
            float4 v = xr[i];
            asm volatile("red.global.add.v4.f32 [%0], {%1, %2, %3, %4};"
                         :: "l"(p + i * 4), "f"(v.x * c), "f"(v.y * c),
                            "f"(v.z * c), "f"(v.w * c)
                         : "memory");
        }
    }
}

// ---------------------------------------------------------------------------
// Kernel 2b: pull. Warp per dst node; fp16 gathers, fp32 accumulate,
// single red.global.add.v4 per lane (composes with overflow fallback).
// ---------------------------------------------------------------------------
__global__ void pull_kernel(int N) {
    int node = (blockIdx.x * blockDim.x + threadIdx.x) >> 5;
    int lane = threadIdx.x & 31;
    if (node >= N) return;

    int cnt = g_cnt[node];
    if (cnt > CAP) cnt = CAP;
    if (cnt == 0) return;

    const uint2* b = g_bucket + (size_t)node * CAP;
    float ax = 0.f, ay = 0.f, az = 0.f, aw = 0.f;
    for (int j = 0; j < cnt; j++) {
        uint2 pe = b[j];  // lane-uniform
        float c = __uint_as_float(pe.y);
        uint2 hw = reinterpret_cast<const uint2*>(g_x_h + (size_t)pe.x * D)[lane];
        float2 f01 = __half22float2(*reinterpret_cast<__half2*>(&hw.x));
        float2 f23 = __half22float2(*reinterpret_cast<__half2*>(&hw.y));
        ax = fmaf(c, f01.x, ax);
        ay = fmaf(c, f01.y, ay);
        az = fmaf(c, f23.x, az);
        aw = fmaf(c, f23.y, aw);
    }
    float* p = g_agg + (size_t)node * D + lane * 4;
    asm volatile("red.global.add.v4.f32 [%0], {%1, %2, %3, %4};"
                 :: "l"(p), "f"(ax), "f"(ay), "f"(az), "f"(aw)
                 : "memory");
}

// ---------------------------------------------------------------------------
// Kernel 3: out = relu(agg) @ W^T + b via bf16x3 mma.m16n8k16, 2 CTAs/SM.
// Tiles of 64 rows; W hi/lo resident in smem per CTA (packed bf16x2).
// ---------------------------------------------------------------------------
#define PITCH 68   // words per row (64 + 4 pad) -> conflict-free fragments

#define SM_WHI 0
#define SM_WLO (128 * PITCH)
#define SM_AHI (2 * 128 * PITCH)
#define SM_ALO (2 * 128 * PITCH + 64 * PITCH)
#define SM_WORDS (2 * 128 * PITCH + 2 * 64 * PITCH)

__device__ __forceinline__ void mma_bf16(float* d, const uint32_t* a, const uint32_t* b) {
    asm volatile(
        "mma.sync.aligned.m16n8k16.row.col.f32.bf16.bf16.f32 "
        "{%0,%1,%2,%3}, {%4,%5,%6,%7}, {%8,%9}, {%0,%1,%2,%3};"
        : "+f"(d[0]), "+f"(d[1]), "+f"(d[2]), "+f"(d[3])
        : "r"(a[0]), "r"(a[1]), "r"(a[2]), "r"(a[3]), "r"(b[0]), "r"(b[1]));
}

__global__ __launch_bounds__(256, 2)
void gemm_kernel(const float* __restrict__ bias,
                 float* __restrict__ out,
                 int N) {
    extern __shared__ uint32_t sm[];
    int tid = threadIdx.x;
    int lane = tid & 31;
    int wid = tid >> 5;
    int warpM = wid >> 2;   // 0..1 (32 rows)
    int warpN = wid & 3;    // 0..3 (32 cols)

    // ---- load packed W hi/lo into smem once ----
    for (int i = tid; i < 128 * 16; i += 256) {
        int r = i >> 4;
        int c4 = i & 15;
        uint4 h = reinterpret_cast<const uint4*>(g_W_hi)[(size_t)r * 16 + c4];
        uint4 l = reinterpret_cast<const uint4*>(g_W_lo)[(size_t)r * 16 + c4];
        *reinterpret_cast<uint4*>(&sm[SM_WHI + r * PITCH + c4 * 4]) = h;
        *reinterpret_cast<uint4*>(&sm[SM_WLO + r * PITCH + c4 * 4]) = l;
    }

    float bv[4][2];
#pragma unroll
    for (int nt = 0; nt < 4; nt++) {
        int col = warpN * 32 + nt * 8 + (lane & 3) * 2;
        bv[nt][0] = bias[col];
        bv[nt][1] = bias[col + 1];
    }
    __syncthreads();

    int ntiles = (N + 63) >> 6;
    for (int t = blockIdx.x; t < ntiles; t += gridDim.x) {
        int m0 = t << 6;

        // ---- fill A tile: relu + bf16 hi/lo split, packed pairs ----
        for (int i = tid; i < 64 * 32; i += 256) {
            int r = i >> 5;
            int c4 = i & 31;           // float4 chunk: elements 4*c4..4*c4+3
            int row = m0 + r;
            float4 v;
            if (row < N)
                v = *reinterpret_cast<const float4*>(g_agg + (size_t)row * D + c4 * 4);
            else
                v = make_float4(0.f, 0.f, 0.f, 0.f);
            float a0 = fmaxf(v.x, 0.f), a1 = fmaxf(v.y, 0.f);
            float a2 = fmaxf(v.z, 0.f), a3 = fmaxf(v.w, 0.f);
            __nv_bfloat16 h0 = __float2bfloat16_rn(a0);
            __nv_bfloat16 h1 = __float2bfloat16_rn(a1);
            __nv_bfloat16 h2 = __float2bfloat16_rn(a2);
            __nv_bfloat16 h3 = __float2bfloat16_rn(a3);
            __nv_bfloat162 hp0 = __halves2bfloat162(h0, h1);
            __nv_bfloat162 hp1 = __halves2bfloat162(h2, h3);
            __nv_bfloat162 lp0 = __halves2bfloat162(
                __float2bfloat16_rn(a0 - __bfloat162float(h0)),
                __float2bfloat16_rn(a1 - __bfloat162float(h1)));
            __nv_bfloat162 lp1 = __halves2bfloat162(
                __float2bfloat16_rn(a2 - __bfloat162float(h2)),
                __float2bfloat16_rn(a3 - __bfloat162float(h3)));
            uint2 hw = make_uint2(*reinterpret_cast<uint32_t*>(&hp0),
                                  *reinterpret_cast<uint32_t*>(&hp1));
            uint2 lw = make_uint2(*reinterpret_cast<uint32_t*>(&lp0),
                                  *reinterpret_cast<uint32_t*>(&lp1));
            *reinterpret_cast<uint2*>(&sm[SM_AHI + r * PITCH + c4 * 2]) = hw;
            *reinterpret_cast<uint2*>(&sm[SM_ALO + r * PITCH + c4 * 2]) = lw;
        }
        __syncthreads();

        float acc[2][4][4];
#pragma unroll
        for (int mt = 0; mt < 2; mt++)
#pragma unroll
            for (int nt = 0; nt < 4; nt++)
#pragma unroll
                for (int i = 0; i < 4; i++) acc[mt][nt][i] = 0.f;

#pragma unroll
        for (int ks = 0; ks < 8; ks++) {
            int w0 = ks * 8 + (lane & 3);
            uint32_t ahi[2][4], alo[2][4];
#pragma unroll
            for (int mt = 0; mt < 2; mt++) {
                int r = warpM * 32 + mt * 16 + (lane >> 2);
                ahi[mt][0] = sm[SM_AHI + r * PITCH + w0];
                ahi[mt][1] = sm[SM_AHI + (r + 8) * PITCH + w0];
                ahi[mt][2] = sm[SM_AHI + r * PITCH + w0 + 4];
                ahi[mt][3] = sm[SM_AHI + (r + 8) * PITCH + w0 + 4];
                alo[mt][0] = sm[SM_ALO + r * PITCH + w0];
                alo[mt][1] = sm[SM_ALO + (r + 8) * PITCH + w0];
                alo[mt][2] = sm[SM_ALO + r * PITCH + w0 + 4];
                alo[mt][3] = sm[SM_ALO + (r + 8) * PITCH + w0 + 4];
            }
            uint32_t bhi[4][2], blo[4][2];
#pragma unroll
            for (int nt = 0; nt < 4; nt++) {
                int n = warpN * 32 + nt * 8 + (lane >> 2);
                bhi[nt][0] = sm[SM_WHI + n * PITCH + w0];
                bhi[nt][1] = sm[SM_WHI + n * PITCH + w0 + 4];
                blo[nt][0] = sm[SM_WLO + n * PITCH + w0];
                blo[nt][1] = sm[SM_WLO + n * PITCH + w0 + 4];
            }
#pragma unroll
            for (int mt = 0; mt < 2; mt++)
#pragma unroll
                for (int nt = 0; nt < 4; nt++) {
                    mma_bf16(acc[mt][nt], ahi[mt], blo[nt]);
                    mma_bf16(acc[mt][nt], alo[mt], bhi[nt]);
                    mma_bf16(acc[mt][nt], ahi[mt], bhi[nt]);
                }
        }

#pragma unroll
        for (int mt = 0; mt < 2; mt++) {
            int r0 = m0 + warpM * 32 + mt * 16 + (lane >> 2);
#pragma unroll
            for (int nt = 0; nt < 4; nt++) {
                int col = warpN * 32 + nt * 8 + (lane & 3) * 2;
                if (r0 < N) {
                    float2 v = make_float2(acc[mt][nt][0] + bv[nt][0],
                                           acc[mt][nt][1] + bv[nt][1]);
                    *reinterpret_cast<float2*>(out + (size_t)r0 * OUTD + col) = v;
                }
                if (r0 + 8 < N) {
                    float2 v = make_float2(acc[mt][nt][2] + bv[nt][0],
                                           acc[mt][nt][3] + bv[nt][1]);
                    *reinterpret_cast<float2*>(out + (size_t)(r0 + 8) * OUTD + col) = v;
                }
            }
        }
        __syncthreads();
    }
}

// ---------------------------------------------------------------------------
// Launch
// ---------------------------------------------------------------------------
extern "C" void kernel_launch(void* const* d_in, const int* in_sizes, int n_in,
                              void* d_out, int out_size) {
    const float* x      = (const float*)d_in[0];
    const float* x0     = (const float*)d_in[1];
    const float* ew     = (const float*)d_in[2];
    const float* att_l  = (const float*)d_in[3];
    const float* att_r  = (const float*)d_in[4];
    const float* W      = (const float*)d_in[5];
    const float* bias   = (const float*)d_in[6];
    const void*  ei     = (const void*)d_in[7];
    float* out = (float*)d_out;

    int N = in_sizes[1] / D;
    int E = in_sizes[2];

    static bool attr_set = false;
    if (!attr_set) {
        cudaFuncSetAttribute(gemm_kernel,
                             cudaFuncAttributeMaxDynamicSharedMemorySize,
                             SM_WORDS * 4);
        attr_set = true;
    }

    int nzero = (N + 255) / 256;
    prep_kernel<<<32 + nzero + 1, 256>>>(W, (const unsigned int*)ei, N, E, nzero);
    {
        int blocks = (N + 7) / 8;
        alpha_init_kernel<<<blocks, 256>>>(x, x0, att_l, att_r, N);
    }
    fill_kernel<<<(E + 255) / 256, 256>>>(x, ei, ew, E);
    {
        int blocks = (N + 7) / 8;
        pull_kernel<<<blocks, 256>>>(N);
    }
    gemm_kernel<<<296, 256, SM_WORDS * 4>>>(bias, out, N);
}